// round 1
// baseline (speedup 1.0000x reference)
#include <cuda_runtime.h>

#define N_NODES 100000
#define N_EDGES 1600000
#define F_IN 16
#define F_MID 32
#define F_OUT 2

// Scratch (device globals: no allocation allowed in kernel_launch)
__device__ float g_deg[N_NODES];
__device__ float g_dis[N_NODES];
__device__ float g_h1s[N_NODES * F_MID];   // dis[v] * (x@W1)
__device__ float g_A  [N_NODES * F_MID];   // layer-1 accumulator
__device__ float g_h2s[N_NODES * F_OUT];   // dis[v] * (relu(..)@W2)
__device__ float g_A2 [N_NODES * F_OUT];   // layer-2 accumulator

// --- degree with self loops: deg[v] = 1 + #edges with dst==v ---
__global__ void k_deg_init() {
    int v = blockIdx.x * blockDim.x + threadIdx.x;
    if (v < N_NODES) g_deg[v] = 1.0f;
}

__global__ void k_deg_count(const int* __restrict__ ei) {
    int e = blockIdx.x * blockDim.x + threadIdx.x;
    if (e < N_EDGES) atomicAdd(&g_deg[ei[N_EDGES + e]], 1.0f);
}

// --- layer 1 GEMM: h1s[v][c] = dis[v] * sum_k x[v][k]*W1[k][c]; A init = h1s ---
__global__ void k_layer1_gemm(const float* __restrict__ x, const float* __restrict__ W1) {
    __shared__ float sW[F_IN * F_MID];
    int t = threadIdx.x;
    for (int i = t; i < F_IN * F_MID; i += blockDim.x) sW[i] = W1[i];
    __syncthreads();
    long idx = (long)blockIdx.x * blockDim.x + t;
    if (idx >= (long)N_NODES * F_MID) return;
    int v = (int)(idx >> 5);
    int c = (int)(idx & 31);
    float dis = rsqrtf(g_deg[v]);
    if (c == 0) g_dis[v] = dis;
    const float* xr = x + v * F_IN;
    float acc = 0.0f;
#pragma unroll
    for (int k = 0; k < F_IN; k++) acc = fmaf(xr[k], sW[k * F_MID + c], acc);
    float hs = dis * acc;
    g_h1s[idx] = hs;
    g_A[idx]   = hs;   // self-loop contribution
}

// --- layer 1 edge aggregation: warp per edge, lane = feature column ---
__global__ void k_edge1(const int* __restrict__ ei) {
    long idx = (long)blockIdx.x * blockDim.x + threadIdx.x;
    long e = idx >> 5;
    if (e >= N_EDGES) return;
    int lane = (int)(idx & 31);
    int src = ei[e];
    int dst = ei[N_EDGES + e];
    float val = g_h1s[(long)src * F_MID + lane];
    atomicAdd(&g_A[(long)dst * F_MID + lane], val);
}

// --- layer 1 epilogue + layer 2 GEMM fused: thread per node ---
__global__ void k_layer2(const float* __restrict__ b1, const float* __restrict__ W2) {
    __shared__ float sW[F_MID * F_OUT];
    __shared__ float sb1[F_MID];
    int t = threadIdx.x;
    if (t < F_MID * F_OUT) sW[t] = W2[t];
    if (t < F_MID) sb1[t] = b1[t];
    __syncthreads();
    int v = blockIdx.x * blockDim.x + t;
    if (v >= N_NODES) return;
    float dis = g_dis[v];
    float acc0 = 0.0f, acc1 = 0.0f;
    const float4* Ar = (const float4*)(g_A + (long)v * F_MID);
#pragma unroll
    for (int q = 0; q < 8; q++) {
        float4 a4 = Ar[q];
        float vv[4] = {a4.x, a4.y, a4.z, a4.w};
#pragma unroll
        for (int r = 0; r < 4; r++) {
            int j = q * 4 + r;
            float h = fmaxf(fmaf(dis, vv[r], sb1[j]), 0.0f);   // relu(dis*A + b1)
            acc0 = fmaf(h, sW[j * 2 + 0], acc0);
            acc1 = fmaf(h, sW[j * 2 + 1], acc1);
        }
    }
    float s0 = dis * acc0, s1 = dis * acc1;
    g_h2s[(long)v * 2 + 0] = s0;
    g_h2s[(long)v * 2 + 1] = s1;
    g_A2 [(long)v * 2 + 0] = s0;   // self-loop contribution
    g_A2 [(long)v * 2 + 1] = s1;
}

// --- layer 2 edge aggregation: 2 threads per edge ---
__global__ void k_edge2(const int* __restrict__ ei) {
    long idx = (long)blockIdx.x * blockDim.x + threadIdx.x;
    long e = idx >> 1;
    if (e >= N_EDGES) return;
    int c = (int)(idx & 1);
    int src = ei[e];
    int dst = ei[N_EDGES + e];
    atomicAdd(&g_A2[(long)dst * 2 + c], g_h2s[(long)src * 2 + c]);
}

// --- final: out = dis*A2 + b2 ---
__global__ void k_out(const float* __restrict__ b2, float* __restrict__ out) {
    int idx = blockIdx.x * blockDim.x + threadIdx.x;
    if (idx >= N_NODES * F_OUT) return;
    int v = idx >> 1;
    int c = idx & 1;
    out[idx] = fmaf(g_dis[v], g_A2[idx], b2[c]);
}

extern "C" void kernel_launch(void* const* d_in, const int* in_sizes, int n_in,
                              void* d_out, int out_size) {
    const float* x  = (const float*)d_in[0];
    const int*   ei = (const int*)  d_in[1];
    const float* W1 = (const float*)d_in[2];
    const float* b1 = (const float*)d_in[3];
    const float* W2 = (const float*)d_in[4];
    const float* b2 = (const float*)d_in[5];
    float* out = (float*)d_out;

    const int T = 256;
    k_deg_init<<<(N_NODES + T - 1) / T, T>>>();
    k_deg_count<<<(N_EDGES + T - 1) / T, T>>>(ei);
    {
        long n = (long)N_NODES * F_MID;
        k_layer1_gemm<<<(unsigned)((n + T - 1) / T), T>>>(x, W1);
    }
    {
        long n = (long)N_EDGES * 32;
        k_edge1<<<(unsigned)((n + T - 1) / T), T>>>(ei);
    }
    k_layer2<<<(N_NODES + T - 1) / T, T>>>(b1, W2);
    {
        long n = (long)N_EDGES * 2;
        k_edge2<<<(unsigned)((n + T - 1) / T), T>>>(ei);
    }
    k_out<<<(N_NODES * F_OUT + T - 1) / T, T>>>(b2, out);
}

// round 2
// speedup vs baseline: 2.4651x; 2.4651x over previous
#include <cuda_runtime.h>

#define N_NODES 100000
#define N_EDGES 1600000
#define F_IN 16
#define F_MID 32
#define F_OUT 2

// Scratch (device globals; 16B-aligned for vector ld/red)
__device__ float g_deg[N_NODES];
__device__ float g_dis[N_NODES];
__device__ __align__(16) float g_xs [N_NODES * F_IN];   // dis[v] * x[v]
__device__ __align__(16) float g_AX [N_NODES * F_IN];   // aggregated scaled X
__device__ __align__(16) float g_h2s[N_NODES * F_OUT];  // dis[v] * (relu(..)@W2)
__device__ __align__(16) float g_A2 [N_NODES * F_OUT];  // layer-2 accumulator

// --- degree with self loops ---
__global__ void k_deg_init() {
    int v = blockIdx.x * blockDim.x + threadIdx.x;
    if (v < N_NODES) g_deg[v] = 1.0f;
}

__global__ void k_deg_count(const int* __restrict__ ei) {
    int e = blockIdx.x * blockDim.x + threadIdx.x;
    if (e < N_EDGES) atomicAdd(&g_deg[ei[N_EDGES + e]], 1.0f);
}

// --- pre: dis[v] = rsqrt(deg); xs = dis*x; AX init = xs (self loop) ---
// 4 threads per node, one float4 each -> fully coalesced.
__global__ void k_pre(const float* __restrict__ x) {
    long idx = (long)blockIdx.x * blockDim.x + threadIdx.x;
    if (idx >= (long)N_NODES * 4) return;
    int v = (int)(idx >> 2);
    int q = (int)(idx & 3);
    float dis = rsqrtf(g_deg[v]);
    if (q == 0) g_dis[v] = dis;
    float4 xv = *(const float4*)(x + (long)v * F_IN + q * 4);
    xv.x *= dis; xv.y *= dis; xv.z *= dis; xv.w *= dis;
    *(float4*)(g_xs + (long)v * F_IN + q * 4) = xv;
    *(float4*)(g_AX + (long)v * F_IN + q * 4) = xv;
}

// --- layer-1 edge aggregation in INPUT space: 4 lanes per edge ---
// lane q moves floats [4q, 4q+4) of the 16-dim scaled-X row via one
// LDG.128 + one red.global.add.v4.f32.
__global__ void k_edge1(const int* __restrict__ ei) {
    long idx = (long)blockIdx.x * blockDim.x + threadIdx.x;
    long e = idx >> 2;
    if (e >= N_EDGES) return;
    int q = (int)(idx & 3);
    int src = __ldg(ei + e);
    int dst = __ldg(ei + N_EDGES + e);
    float4 v = *(const float4*)(g_xs + (long)src * F_IN + q * 4);
    float* p = g_AX + (long)dst * F_IN + q * 4;
    asm volatile("red.global.add.v4.f32 [%0], {%1, %2, %3, %4};"
                 :: "l"(p), "f"(v.x), "f"(v.y), "f"(v.z), "f"(v.w) : "memory");
}

// --- fused epilogue: h1 = relu(dis*(AX@W1)+b1); h2s = dis*(h1@W2); A2 init ---
__global__ void k_layer2(const float* __restrict__ W1, const float* __restrict__ b1,
                         const float* __restrict__ W2) {
    __shared__ float sW1[F_IN * F_MID];
    __shared__ float sb1[F_MID];
    __shared__ float sW2[F_MID * F_OUT];
    int t = threadIdx.x;
    for (int i = t; i < F_IN * F_MID; i += blockDim.x) sW1[i] = W1[i];
    if (t < F_MID) sb1[t] = b1[t];
    if (t < F_MID * F_OUT) sW2[t] = W2[t];
    __syncthreads();
    int v = blockIdx.x * blockDim.x + t;
    if (v >= N_NODES) return;
    float dis = g_dis[v];

    float ax[F_IN];
    const float4* Ar = (const float4*)(g_AX + (long)v * F_IN);
#pragma unroll
    for (int q = 0; q < 4; q++) {
        float4 a4 = Ar[q];
        ax[q * 4 + 0] = a4.x; ax[q * 4 + 1] = a4.y;
        ax[q * 4 + 2] = a4.z; ax[q * 4 + 3] = a4.w;
    }

    float h[F_MID];
#pragma unroll
    for (int j = 0; j < F_MID; j++) h[j] = 0.0f;
#pragma unroll
    for (int k = 0; k < F_IN; k++) {
        float a = ax[k];
#pragma unroll
        for (int j = 0; j < F_MID; j++) h[j] = fmaf(a, sW1[k * F_MID + j], h[j]);
    }

    float acc0 = 0.0f, acc1 = 0.0f;
#pragma unroll
    for (int j = 0; j < F_MID; j++) {
        float hj = fmaxf(fmaf(dis, h[j], sb1[j]), 0.0f);
        acc0 = fmaf(hj, sW2[j * 2 + 0], acc0);
        acc1 = fmaf(hj, sW2[j * 2 + 1], acc1);
    }
    float s0 = dis * acc0, s1 = dis * acc1;
    float2 s = make_float2(s0, s1);
    *(float2*)(g_h2s + (long)v * 2) = s;
    *(float2*)(g_A2  + (long)v * 2) = s;   // self-loop contribution
}

// --- layer-2 edge aggregation: 1 thread per edge, vector red ---
__global__ void k_edge2(const int* __restrict__ ei) {
    long e = (long)blockIdx.x * blockDim.x + threadIdx.x;
    if (e >= N_EDGES) return;
    int src = __ldg(ei + e);
    int dst = __ldg(ei + N_EDGES + e);
    float2 v = *(const float2*)(g_h2s + (long)src * 2);
    float* p = g_A2 + (long)dst * 2;
    asm volatile("red.global.add.v2.f32 [%0], {%1, %2};"
                 :: "l"(p), "f"(v.x), "f"(v.y) : "memory");
}

// --- final: out = dis*A2 + b2 ---
__global__ void k_out(const float* __restrict__ b2, float* __restrict__ out) {
    int idx = blockIdx.x * blockDim.x + threadIdx.x;
    if (idx >= N_NODES * F_OUT) return;
    int v = idx >> 1;
    int c = idx & 1;
    out[idx] = fmaf(g_dis[v], g_A2[idx], b2[c]);
}

extern "C" void kernel_launch(void* const* d_in, const int* in_sizes, int n_in,
                              void* d_out, int out_size) {
    const float* x  = (const float*)d_in[0];
    const int*   ei = (const int*)  d_in[1];
    const float* W1 = (const float*)d_in[2];
    const float* b1 = (const float*)d_in[3];
    const float* W2 = (const float*)d_in[4];
    const float* b2 = (const float*)d_in[5];
    float* out = (float*)d_out;

    const int T = 256;
    k_deg_init<<<(N_NODES + T - 1) / T, T>>>();
    k_deg_count<<<(N_EDGES + T - 1) / T, T>>>(ei);
    {
        long n = (long)N_NODES * 4;
        k_pre<<<(unsigned)((n + T - 1) / T), T>>>(x);
    }
    {
        long n = (long)N_EDGES * 4;
        k_edge1<<<(unsigned)((n + T - 1) / T), T>>>(ei);
    }
    k_layer2<<<(N_NODES + T - 1) / T, T>>>(W1, b1, W2);
    k_edge2<<<(N_EDGES + T - 1) / T, T>>>(ei);
    k_out<<<(N_NODES * F_OUT + T - 1) / T, T>>>(b2, out);
}